// round 6
// baseline (speedup 1.0000x reference)
#include <cuda_runtime.h>
#include <math.h>

#define BSZ 64
#define SSZ 512
#define ISZ 512
#define HSZ 1024
#define G4  4096
#define KSPLIT 4
#define KCH (HSZ / KSPLIT)   // 256
#define NBLK 128             // persistent grid (32 row-tiles x 4 k-splits)

typedef unsigned long long u64;

// Scratch (allocation-free rule: __device__ globals)
__device__ float g_gx[(size_t)SSZ * BSZ * G4];      // [S][B][4H]
__device__ float g_part[(size_t)KSPLIT * BSZ * G4]; // [KS][B][4H]
__device__ float g_c[BSZ * HSZ];                    // cell state

// Grid barrier state
__device__ unsigned g_bar_count = 0;
__device__ unsigned g_bar_gen   = 0;

// ---------------- packed f32x2 helpers ----------------
__device__ __forceinline__ u64 pack2(float x, float y) {
    u64 r;
    asm("mov.b64 %0, {%1, %2};" : "=l"(r) : "f"(x), "f"(y));
    return r;
}
__device__ __forceinline__ void unpack2(u64 v, float& x, float& y) {
    asm("mov.b64 {%0, %1}, %2;" : "=f"(x), "=f"(y) : "l"(v));
}
__device__ __forceinline__ u64 fma2(u64 a, u64 b, u64 c) {
    u64 d;
    asm("fma.rn.f32x2 %0, %1, %2, %3;" : "=l"(d) : "l"(a), "l"(b), "l"(c));
    return d;
}

// Sense-reversing grid barrier (all 128 blocks co-resident: 1 block/SM).
__device__ __forceinline__ void grid_barrier() {
    __syncthreads();
    if (threadIdx.x == 0) {
        __threadfence();
        unsigned my = *(volatile unsigned*)&g_bar_gen;
        if (atomicAdd(&g_bar_count, 1) == NBLK - 1) {
            atomicExch(&g_bar_count, 0);
            __threadfence();
            *(volatile unsigned*)&g_bar_gen = my + 1;
        } else {
            while (*(volatile unsigned*)&g_bar_gen == my) { }
        }
        __threadfence();
    }
    __syncthreads();
}

// ============================================================================
// Phase A: gx[m][n] = sum_k x_row(m)[k]*w_ih[n][k] + b_ih[n] + b_hh[n]
// Tile 128m x 128n, BK=16, double-buffered. B operand stored DUPLICATED as
// (v,v) u64 pairs -> inner loop is pure LDS.128 + FFMA2 (no pack movs).
// ============================================================================
__global__ void __launch_bounds__(256) gx_gemm(
    const float* __restrict__ x,
    const float* __restrict__ wih,
    const float* __restrict__ bih,
    const float* __restrict__ bhh)
{
    __shared__ float As[2][16][128];   // [stage][k][m]          16 KB
    __shared__ u64   Bsd[2][16][128];  // [stage][k][n] dup pairs 32 KB

    const int t  = threadIdx.x;
    const int mt = t & 15;             // 16 m-groups of 8
    const int nt = t >> 4;             // 16 n-groups of 8
    const int n0 = blockIdx.x * 128;
    const int m0 = blockIdx.y * 128;

    const int lr = t >> 1;             // 0..127
    const int lq = (t & 1) * 8;        // k offset 0 / 8
    const int m  = m0 + lr;
    const float* asrc = x   + ((size_t)(m & 63) * SSZ + (m >> 6)) * ISZ + lq;
    const float* bsrc = wih + (size_t)(n0 + lr) * ISZ + lq;

    u64 acc[4][8];
#pragma unroll
    for (int p = 0; p < 4; p++)
#pragma unroll
        for (int j = 0; j < 8; j++) acc[p][j] = 0ULL;

    float4 ab[2], bb[2];
#pragma unroll
    for (int q = 0; q < 2; q++) {
        ab[q] = *(const float4*)(asrc + q * 4);
        bb[q] = *(const float4*)(bsrc + q * 4);
    }
#pragma unroll
    for (int q = 0; q < 2; q++) {
        As[0][lq + q*4 + 0][lr] = ab[q].x; As[0][lq + q*4 + 1][lr] = ab[q].y;
        As[0][lq + q*4 + 2][lr] = ab[q].z; As[0][lq + q*4 + 3][lr] = ab[q].w;
        Bsd[0][lq + q*4 + 0][lr] = pack2(bb[q].x, bb[q].x);
        Bsd[0][lq + q*4 + 1][lr] = pack2(bb[q].y, bb[q].y);
        Bsd[0][lq + q*4 + 2][lr] = pack2(bb[q].z, bb[q].z);
        Bsd[0][lq + q*4 + 3][lr] = pack2(bb[q].w, bb[q].w);
    }
    __syncthreads();

    const int NTILES = ISZ / 16;       // 32
    for (int tile = 0; tile < NTILES; tile++) {
        const int st = tile & 1;
        if (tile + 1 < NTILES) {
#pragma unroll
            for (int q = 0; q < 2; q++) {
                ab[q] = *(const float4*)(asrc + (tile + 1) * 16 + q * 4);
                bb[q] = *(const float4*)(bsrc + (tile + 1) * 16 + q * 4);
            }
        }
#pragma unroll
        for (int kk = 0; kk < 16; kk++) {
            ulonglong2 a01 = *(const ulonglong2*)&As[st][kk][mt * 8];
            ulonglong2 a23 = *(const ulonglong2*)&As[st][kk][mt * 8 + 4];
            ulonglong2 b01 = *(const ulonglong2*)&Bsd[st][kk][nt * 8];
            ulonglong2 b23 = *(const ulonglong2*)&Bsd[st][kk][nt * 8 + 2];
            ulonglong2 b45 = *(const ulonglong2*)&Bsd[st][kk][nt * 8 + 4];
            ulonglong2 b67 = *(const ulonglong2*)&Bsd[st][kk][nt * 8 + 6];
            u64 hp[4] = {a01.x, a01.y, a23.x, a23.y};
            u64 wd[8] = {b01.x, b01.y, b23.x, b23.y, b45.x, b45.y, b67.x, b67.y};
#pragma unroll
            for (int j = 0; j < 8; j++)
#pragma unroll
                for (int p = 0; p < 4; p++) acc[p][j] = fma2(hp[p], wd[j], acc[p][j]);
        }
        if (tile + 1 < NTILES) {
            const int so = st ^ 1;
#pragma unroll
            for (int q = 0; q < 2; q++) {
                As[so][lq + q*4 + 0][lr] = ab[q].x; As[so][lq + q*4 + 1][lr] = ab[q].y;
                As[so][lq + q*4 + 2][lr] = ab[q].z; As[so][lq + q*4 + 3][lr] = ab[q].w;
                Bsd[so][lq + q*4 + 0][lr] = pack2(bb[q].x, bb[q].x);
                Bsd[so][lq + q*4 + 1][lr] = pack2(bb[q].y, bb[q].y);
                Bsd[so][lq + q*4 + 2][lr] = pack2(bb[q].z, bb[q].z);
                Bsd[so][lq + q*4 + 3][lr] = pack2(bb[q].w, bb[q].w);
            }
        }
        __syncthreads();
    }

    const int nb = n0 + nt * 8;
    float4 bi0 = *(const float4*)&bih[nb];
    float4 bi1 = *(const float4*)&bih[nb + 4];
    float4 bh0 = *(const float4*)&bhh[nb];
    float4 bh1 = *(const float4*)&bhh[nb + 4];
    float bias[8] = {bi0.x + bh0.x, bi0.y + bh0.y, bi0.z + bh0.z, bi0.w + bh0.w,
                     bi1.x + bh1.x, bi1.y + bh1.y, bi1.z + bh1.z, bi1.w + bh1.w};
#pragma unroll
    for (int p = 0; p < 4; p++) {
        float lo[8], hi[8];
#pragma unroll
        for (int j = 0; j < 8; j++) unpack2(acc[p][j], lo[j], hi[j]);
        const int mrow = m0 + mt * 8 + p * 2;
        float* d0 = &g_gx[(size_t)mrow * G4 + nb];
        *(float4*)d0       = make_float4(lo[0]+bias[0], lo[1]+bias[1], lo[2]+bias[2], lo[3]+bias[3]);
        *(float4*)(d0 + 4) = make_float4(lo[4]+bias[4], lo[5]+bias[5], lo[6]+bias[6], lo[7]+bias[7]);
        float* d1 = d0 + G4;
        *(float4*)d1       = make_float4(hi[0]+bias[0], hi[1]+bias[1], hi[2]+bias[2], hi[3]+bias[3]);
        *(float4*)(d1 + 4) = make_float4(hi[4]+bias[4], hi[5]+bias[5], hi[6]+bias[6], hi[7]+bias[7]);
    }
}

// ============================================================================
// Persistent recurrence, ONE launch, 256 threads/block (2 warps/SMSP).
// Per step: split-K GEMM (64b x 128r x 256k per block, thread tile 8b x 4r,
// w operand pre-duplicated in smem), barrier, distributed combine, barrier.
// ============================================================================
__global__ void __launch_bounds__(256) lstm_persist(
    const float* __restrict__ whh,
    float* out)
{
    __shared__ float Hs[2][16][64];    // [stage][k][b]            8 KB
    __shared__ u64   Wsd[2][16][128];  // [stage][k][r] dup pairs 32 KB

    const int t  = threadIdx.x;
    const int bt = t & 7;              // 8 b-groups of 8
    const int rt = t >> 3;             // 32 r-groups of 4
    const int rtile = blockIdx.x >> 2;
    const int ks    = blockIdx.x & 3;
    const int r0    = rtile * 128;
    const int kbase = ks * KCH;

    // Loaders: W 2 thr/row (8 floats each); H 4 thr/row (4 floats each)
    const int lr  = t >> 1;            // 0..127
    const int lq  = (t & 1) * 8;
    const int hb4 = t >> 2;            // 0..63
    const int hq4 = (t & 3) * 4;
    const float* wsrc = whh + (size_t)(r0 + lr) * HSZ + kbase + lq;

    const int ebase = blockIdx.x * 512;

    for (int s = 0; s < SSZ; s++) {
        if (s > 0) {
            const float* hsrc = out + (size_t)(s - 1) * (BSZ * HSZ)
                              + (size_t)hb4 * HSZ + kbase + hq4;

            u64 acc[4][4];
#pragma unroll
            for (int p = 0; p < 4; p++)
#pragma unroll
                for (int j = 0; j < 4; j++) acc[p][j] = 0ULL;

            float4 hbuf, wbuf[2];
            hbuf = __ldcg((const float4*)hsrc);
#pragma unroll
            for (int q = 0; q < 2; q++) wbuf[q] = *(const float4*)(wsrc + q * 4);

            Hs[0][hq4 + 0][hb4] = hbuf.x; Hs[0][hq4 + 1][hb4] = hbuf.y;
            Hs[0][hq4 + 2][hb4] = hbuf.z; Hs[0][hq4 + 3][hb4] = hbuf.w;
#pragma unroll
            for (int q = 0; q < 2; q++) {
                Wsd[0][lq + q*4 + 0][lr] = pack2(wbuf[q].x, wbuf[q].x);
                Wsd[0][lq + q*4 + 1][lr] = pack2(wbuf[q].y, wbuf[q].y);
                Wsd[0][lq + q*4 + 2][lr] = pack2(wbuf[q].z, wbuf[q].z);
                Wsd[0][lq + q*4 + 3][lr] = pack2(wbuf[q].w, wbuf[q].w);
            }
            __syncthreads();

            const int NTILES = KCH / 16;   // 16
            for (int tile = 0; tile < NTILES; tile++) {
                const int st = tile & 1;
                if (tile + 1 < NTILES) {
                    hbuf = __ldcg((const float4*)(hsrc + (tile + 1) * 16));
#pragma unroll
                    for (int q = 0; q < 2; q++)
                        wbuf[q] = *(const float4*)(wsrc + (tile + 1) * 16 + q * 4);
                }
#pragma unroll
                for (int kk = 0; kk < 16; kk++) {
                    ulonglong2 h01 = *(const ulonglong2*)&Hs[st][kk][bt * 8];
                    ulonglong2 h23 = *(const ulonglong2*)&Hs[st][kk][bt * 8 + 4];
                    ulonglong2 w01 = *(const ulonglong2*)&Wsd[st][kk][rt * 4];
                    ulonglong2 w23 = *(const ulonglong2*)&Wsd[st][kk][rt * 4 + 2];
                    u64 hp[4] = {h01.x, h01.y, h23.x, h23.y};
                    u64 wd[4] = {w01.x, w01.y, w23.x, w23.y};
#pragma unroll
                    for (int j = 0; j < 4; j++)
#pragma unroll
                        for (int p = 0; p < 4; p++) acc[p][j] = fma2(hp[p], wd[j], acc[p][j]);
                }
                if (tile + 1 < NTILES) {
                    const int so = st ^ 1;
                    Hs[so][hq4 + 0][hb4] = hbuf.x; Hs[so][hq4 + 1][hb4] = hbuf.y;
                    Hs[so][hq4 + 2][hb4] = hbuf.z; Hs[so][hq4 + 3][hb4] = hbuf.w;
#pragma unroll
                    for (int q = 0; q < 2; q++) {
                        Wsd[so][lq + q*4 + 0][lr] = pack2(wbuf[q].x, wbuf[q].x);
                        Wsd[so][lq + q*4 + 1][lr] = pack2(wbuf[q].y, wbuf[q].y);
                        Wsd[so][lq + q*4 + 2][lr] = pack2(wbuf[q].z, wbuf[q].z);
                        Wsd[so][lq + q*4 + 3][lr] = pack2(wbuf[q].w, wbuf[q].w);
                    }
                }
                __syncthreads();
            }

            // Store partials [ks][b][r]: acc[p][j] -> b = bt*8+2p(+1), r = r0+rt*4+j
            const int rb = r0 + rt * 4;
#pragma unroll
            for (int p = 0; p < 4; p++) {
                float lo[4], hi[4];
#pragma unroll
                for (int j = 0; j < 4; j++) unpack2(acc[p][j], lo[j], hi[j]);
                const int b = bt * 8 + p * 2;
                float* d0 = &g_part[((size_t)ks * BSZ + b) * G4 + rb];
                *(float4*)d0 = make_float4(lo[0], lo[1], lo[2], lo[3]);
                *(float4*)(d0 + G4) = make_float4(hi[0], hi[1], hi[2], hi[3]);
            }
        }

        grid_barrier();   // partials visible -> combine

        // Distributed combine: block handles elements [ebase, ebase+512)
        const float* gxs = g_gx + (size_t)s * (BSZ * G4);
#pragma unroll
        for (int i = t; i < 512; i += 256) {
            const int e = ebase + i;
            const int b = e >> 10;
            const int n = e & 1023;
            float pre[4];
#pragma unroll
            for (int g = 0; g < 4; g++) {
                const int r = g * HSZ + n;
                float v = gxs[(size_t)b * G4 + r];
                if (s > 0) {
#pragma unroll
                    for (int kp = 0; kp < KSPLIT; kp++)
                        v += __ldcg(&g_part[((size_t)kp * BSZ + b) * G4 + r]);
                }
                pre[g] = v;
            }
            const float iv = 1.0f / (1.0f + expf(-pre[0]));
            const float fv = 1.0f / (1.0f + expf(-pre[1]));
            const float gv = tanhf(pre[2]);
            const float ov = 1.0f / (1.0f + expf(-pre[3]));
            const float cp = (s > 0) ? g_c[b * HSZ + n] : 0.0f;
            const float cn = fv * cp + iv * gv;
            const float hn = ov * tanhf(cn);
            g_c[b * HSZ + n] = cn;
            out[((size_t)s * BSZ + b) * HSZ + n] = hn;
            if (s == SSZ - 1) {
                out[((size_t)SSZ       * BSZ + b) * HSZ + n] = hn;  // h_f
                out[((size_t)(SSZ + 1) * BSZ + b) * HSZ + n] = cn;  // c_f
            }
        }

        grid_barrier();   // h(s) visible -> next step
    }
}

extern "C" void kernel_launch(void* const* d_in, const int* in_sizes, int n_in,
                              void* d_out, int out_size)
{
    const float* x   = (const float*)d_in[0];
    const float* wih = (const float*)d_in[1];
    const float* whh = (const float*)d_in[2];
    const float* bih = (const float*)d_in[3];
    const float* bhh = (const float*)d_in[4];
    float* out = (float*)d_out;

    dim3 gridA(G4 / 128, (SSZ * BSZ) / 128);    // (32, 256)
    gx_gemm<<<gridA, 256>>>(x, wih, bih, bhh);

    lstm_persist<<<NBLK, 256>>>(whh, out);

    (void)in_sizes; (void)n_in; (void)out_size;
}

// round 7
// speedup vs baseline: 1.2090x; 1.2090x over previous
#include <cuda_runtime.h>
#include <math.h>

#define BSZ 64
#define SSZ 512
#define ISZ 512
#define HSZ 1024
#define G4  4096
#define KSPLIT 8
#define KCH (HSZ / KSPLIT)   // 128
#define NBLK 128             // persistent grid (16 rtiles x 8 ksplits)

typedef unsigned long long u64;

// Scratch (allocation-free rule: __device__ globals)
__device__ float g_gx[(size_t)SSZ * BSZ * G4];      // [S][B][4H]
__device__ float g_part[(size_t)KSPLIT * BSZ * G4]; // [KS][B][4H]
__device__ float g_c[BSZ * HSZ];                    // cell state

// Grid barrier state
__device__ unsigned g_bar_count = 0;
__device__ unsigned g_bar_gen   = 0;

// ---------------- packed f32x2 helpers ----------------
__device__ __forceinline__ u64 pack2(float x, float y) {
    u64 r;
    asm("mov.b64 %0, {%1, %2};" : "=l"(r) : "f"(x), "f"(y));
    return r;
}
__device__ __forceinline__ void unpack2(u64 v, float& x, float& y) {
    asm("mov.b64 {%0, %1}, %2;" : "=f"(x), "=f"(y) : "l"(v));
}
__device__ __forceinline__ u64 fma2(u64 a, u64 b, u64 c) {
    u64 d;
    asm("fma.rn.f32x2 %0, %1, %2, %3;" : "=l"(d) : "l"(a), "l"(b), "l"(c));
    return d;
}

// Sense-reversing grid barrier (128 blocks, all co-resident: 1 block/SM).
__device__ __forceinline__ void grid_barrier() {
    __syncthreads();
    if (threadIdx.x == 0) {
        __threadfence();
        unsigned my = *(volatile unsigned*)&g_bar_gen;
        if (atomicAdd(&g_bar_count, 1) == NBLK - 1) {
            atomicExch(&g_bar_count, 0);
            __threadfence();
            *(volatile unsigned*)&g_bar_gen = my + 1;
        } else {
            while (*(volatile unsigned*)&g_bar_gen == my) { }
        }
        __threadfence();
    }
    __syncthreads();
}

// ============================================================================
// Phase A: gx = x @ w_ih^T + b. Tile 128m x 128n, BK=16, double-buffered.
// B operand dup-paired in smem (broadcast degree 16 -> dup is cheap here).
// ============================================================================
__global__ void __launch_bounds__(256) gx_gemm(
    const float* __restrict__ x,
    const float* __restrict__ wih,
    const float* __restrict__ bih,
    const float* __restrict__ bhh)
{
    __shared__ float As[2][16][128];   // 16 KB
    __shared__ u64   Bsd[2][16][128];  // 32 KB

    const int t  = threadIdx.x;
    const int mt = t & 15;
    const int nt = t >> 4;
    const int n0 = blockIdx.x * 128;
    const int m0 = blockIdx.y * 128;

    const int lr = t >> 1;
    const int lq = (t & 1) * 8;
    const int m  = m0 + lr;
    const float* asrc = x   + ((size_t)(m & 63) * SSZ + (m >> 6)) * ISZ + lq;
    const float* bsrc = wih + (size_t)(n0 + lr) * ISZ + lq;

    u64 acc[4][8];
#pragma unroll
    for (int p = 0; p < 4; p++)
#pragma unroll
        for (int j = 0; j < 8; j++) acc[p][j] = 0ULL;

    float4 ab[2], bb[2];
#pragma unroll
    for (int q = 0; q < 2; q++) {
        ab[q] = *(const float4*)(asrc + q * 4);
        bb[q] = *(const float4*)(bsrc + q * 4);
    }
#pragma unroll
    for (int q = 0; q < 2; q++) {
        As[0][lq + q*4 + 0][lr] = ab[q].x; As[0][lq + q*4 + 1][lr] = ab[q].y;
        As[0][lq + q*4 + 2][lr] = ab[q].z; As[0][lq + q*4 + 3][lr] = ab[q].w;
        Bsd[0][lq + q*4 + 0][lr] = pack2(bb[q].x, bb[q].x);
        Bsd[0][lq + q*4 + 1][lr] = pack2(bb[q].y, bb[q].y);
        Bsd[0][lq + q*4 + 2][lr] = pack2(bb[q].z, bb[q].z);
        Bsd[0][lq + q*4 + 3][lr] = pack2(bb[q].w, bb[q].w);
    }
    __syncthreads();

    const int NTILES = ISZ / 16;
    for (int tile = 0; tile < NTILES; tile++) {
        const int st = tile & 1;
        if (tile + 1 < NTILES) {
#pragma unroll
            for (int q = 0; q < 2; q++) {
                ab[q] = *(const float4*)(asrc + (tile + 1) * 16 + q * 4);
                bb[q] = *(const float4*)(bsrc + (tile + 1) * 16 + q * 4);
            }
        }
#pragma unroll
        for (int kk = 0; kk < 16; kk++) {
            ulonglong2 a01 = *(const ulonglong2*)&As[st][kk][mt * 8];
            ulonglong2 a23 = *(const ulonglong2*)&As[st][kk][mt * 8 + 4];
            ulonglong2 b01 = *(const ulonglong2*)&Bsd[st][kk][nt * 8];
            ulonglong2 b23 = *(const ulonglong2*)&Bsd[st][kk][nt * 8 + 2];
            ulonglong2 b45 = *(const ulonglong2*)&Bsd[st][kk][nt * 8 + 4];
            ulonglong2 b67 = *(const ulonglong2*)&Bsd[st][kk][nt * 8 + 6];
            u64 hp[4] = {a01.x, a01.y, a23.x, a23.y};
            u64 wd[8] = {b01.x, b01.y, b23.x, b23.y, b45.x, b45.y, b67.x, b67.y};
#pragma unroll
            for (int j = 0; j < 8; j++)
#pragma unroll
                for (int p = 0; p < 4; p++) acc[p][j] = fma2(hp[p], wd[j], acc[p][j]);
        }
        if (tile + 1 < NTILES) {
            const int so = st ^ 1;
#pragma unroll
            for (int q = 0; q < 2; q++) {
                As[so][lq + q*4 + 0][lr] = ab[q].x; As[so][lq + q*4 + 1][lr] = ab[q].y;
                As[so][lq + q*4 + 2][lr] = ab[q].z; As[so][lq + q*4 + 3][lr] = ab[q].w;
                Bsd[so][lq + q*4 + 0][lr] = pack2(bb[q].x, bb[q].x);
                Bsd[so][lq + q*4 + 1][lr] = pack2(bb[q].y, bb[q].y);
                Bsd[so][lq + q*4 + 2][lr] = pack2(bb[q].z, bb[q].z);
                Bsd[so][lq + q*4 + 3][lr] = pack2(bb[q].w, bb[q].w);
            }
        }
        __syncthreads();
    }

    const int nb = n0 + nt * 8;
    float4 bi0 = *(const float4*)&bih[nb];
    float4 bi1 = *(const float4*)&bih[nb + 4];
    float4 bh0 = *(const float4*)&bhh[nb];
    float4 bh1 = *(const float4*)&bhh[nb + 4];
    float bias[8] = {bi0.x + bh0.x, bi0.y + bh0.y, bi0.z + bh0.z, bi0.w + bh0.w,
                     bi1.x + bh1.x, bi1.y + bh1.y, bi1.z + bh1.z, bi1.w + bh1.w};
#pragma unroll
    for (int p = 0; p < 4; p++) {
        float lo[8], hi[8];
#pragma unroll
        for (int j = 0; j < 8; j++) unpack2(acc[p][j], lo[j], hi[j]);
        const int mrow = m0 + mt * 8 + p * 2;
        float* d0 = &g_gx[(size_t)mrow * G4 + nb];
        *(float4*)d0       = make_float4(lo[0]+bias[0], lo[1]+bias[1], lo[2]+bias[2], lo[3]+bias[3]);
        *(float4*)(d0 + 4) = make_float4(lo[4]+bias[4], lo[5]+bias[5], lo[6]+bias[6], lo[7]+bias[7]);
        float* d1 = d0 + G4;
        *(float4*)d1       = make_float4(hi[0]+bias[0], hi[1]+bias[1], hi[2]+bias[2], hi[3]+bias[3]);
        *(float4*)(d1 + 4) = make_float4(hi[4]+bias[4], hi[5]+bias[5], hi[6]+bias[6], hi[7]+bias[7]);
    }
}

// ============================================================================
// Persistent recurrence: 256 threads/block, block tile 64b x 256r x 128k,
// thread tile 8b x 8r (register-packed w dup -> 1 B/MAC smem traffic).
// Grid = 16 rtiles x 8 ksplits. Per step: GEMM, barrier, combine, barrier.
// ============================================================================
__global__ void __launch_bounds__(256) lstm_persist(
    const float* __restrict__ whh,
    float* out)
{
    __shared__ float Hs[2][16][64];    //  8 KB [stage][k][b]
    __shared__ float Ws[2][16][256];   // 32 KB [stage][k][r]

    const int t  = threadIdx.x;
    const int bt = t & 7;              // 8 b-groups of 8
    const int rt = t >> 3;             // 32 r-groups of 8
    const int rtile = blockIdx.x >> 3; // 0..15
    const int ks    = blockIdx.x & 7;  // 0..7
    const int r0    = rtile * 256;
    const int kbase = ks * KCH;

    // Loaders: W 1 thread/row, 16 floats (4 float4); H 4 threads/row, 1 float4
    const int hb4 = t >> 2;            // 0..63
    const int hq4 = (t & 3) * 4;
    const float* wsrc = whh + (size_t)(r0 + t) * HSZ + kbase;

    const int ebase = blockIdx.x * 512;

    for (int s = 0; s < SSZ; s++) {
        if (s > 0) {
            const float* hsrc = out + (size_t)(s - 1) * (BSZ * HSZ)
                              + (size_t)hb4 * HSZ + kbase + hq4;

            u64 acc[4][8];
#pragma unroll
            for (int p = 0; p < 4; p++)
#pragma unroll
                for (int j = 0; j < 8; j++) acc[p][j] = 0ULL;

            float4 hbuf, wbuf[4];
            hbuf = __ldcg((const float4*)hsrc);
#pragma unroll
            for (int q = 0; q < 4; q++) wbuf[q] = *(const float4*)(wsrc + q * 4);

            Hs[0][hq4 + 0][hb4] = hbuf.x; Hs[0][hq4 + 1][hb4] = hbuf.y;
            Hs[0][hq4 + 2][hb4] = hbuf.z; Hs[0][hq4 + 3][hb4] = hbuf.w;
#pragma unroll
            for (int q = 0; q < 4; q++) {
                Ws[0][q*4 + 0][t] = wbuf[q].x; Ws[0][q*4 + 1][t] = wbuf[q].y;
                Ws[0][q*4 + 2][t] = wbuf[q].z; Ws[0][q*4 + 3][t] = wbuf[q].w;
            }
            __syncthreads();

            const int NTILES = KCH / 16;   // 8
            for (int tile = 0; tile < NTILES; tile++) {
                const int st = tile & 1;
                if (tile + 1 < NTILES) {
                    hbuf = __ldcg((const float4*)(hsrc + (tile + 1) * 16));
#pragma unroll
                    for (int q = 0; q < 4; q++)
                        wbuf[q] = *(const float4*)(wsrc + (tile + 1) * 16 + q * 4);
                }
#pragma unroll
                for (int kk = 0; kk < 16; kk++) {
                    ulonglong2 h01 = *(const ulonglong2*)&Hs[st][kk][bt * 8];
                    ulonglong2 h23 = *(const ulonglong2*)&Hs[st][kk][bt * 8 + 4];
                    float4 w0 = *(const float4*)&Ws[st][kk][rt * 8];
                    float4 w1 = *(const float4*)&Ws[st][kk][rt * 8 + 4];
                    u64 hp[4] = {h01.x, h01.y, h23.x, h23.y};
                    u64 wd[8];
                    wd[0] = pack2(w0.x, w0.x); wd[1] = pack2(w0.y, w0.y);
                    wd[2] = pack2(w0.z, w0.z); wd[3] = pack2(w0.w, w0.w);
                    wd[4] = pack2(w1.x, w1.x); wd[5] = pack2(w1.y, w1.y);
                    wd[6] = pack2(w1.z, w1.z); wd[7] = pack2(w1.w, w1.w);
#pragma unroll
                    for (int j = 0; j < 8; j++)
#pragma unroll
                        for (int p = 0; p < 4; p++) acc[p][j] = fma2(hp[p], wd[j], acc[p][j]);
                }
                if (tile + 1 < NTILES) {
                    const int so = st ^ 1;
                    Hs[so][hq4 + 0][hb4] = hbuf.x; Hs[so][hq4 + 1][hb4] = hbuf.y;
                    Hs[so][hq4 + 2][hb4] = hbuf.z; Hs[so][hq4 + 3][hb4] = hbuf.w;
#pragma unroll
                    for (int q = 0; q < 4; q++) {
                        Ws[so][q*4 + 0][t] = wbuf[q].x; Ws[so][q*4 + 1][t] = wbuf[q].y;
                        Ws[so][q*4 + 2][t] = wbuf[q].z; Ws[so][q*4 + 3][t] = wbuf[q].w;
                    }
                }
                __syncthreads();
            }

            // Store partials: acc[p][j] -> b = bt*8 + 2p (+1), r = r0 + rt*8 + j
            const int rb = r0 + rt * 8;
#pragma unroll
            for (int p = 0; p < 4; p++) {
                float lo[8], hi[8];
#pragma unroll
                for (int j = 0; j < 8; j++) unpack2(acc[p][j], lo[j], hi[j]);
                const int b = bt * 8 + p * 2;
                float* d0 = &g_part[((size_t)ks * BSZ + b) * G4 + rb];
                *(float4*)d0       = make_float4(lo[0], lo[1], lo[2], lo[3]);
                *(float4*)(d0 + 4) = make_float4(lo[4], lo[5], lo[6], lo[7]);
                float* d1 = d0 + G4;
                *(float4*)d1       = make_float4(hi[0], hi[1], hi[2], hi[3]);
                *(float4*)(d1 + 4) = make_float4(hi[4], hi[5], hi[6], hi[7]);
            }
        }

        grid_barrier();   // partials visible -> combine

        const float* gxs = g_gx + (size_t)s * (BSZ * G4);
#pragma unroll
        for (int i = t; i < 512; i += 256) {
            const int e = ebase + i;
            const int b = e >> 10;
            const int n = e & 1023;
            float pre[4];
#pragma unroll
            for (int g = 0; g < 4; g++) {
                const int r = g * HSZ + n;
                float v = gxs[(size_t)b * G4 + r];
                if (s > 0) {
#pragma unroll
                    for (int kp = 0; kp < KSPLIT; kp++)
                        v += __ldcg(&g_part[((size_t)kp * BSZ + b) * G4 + r]);
                }
                pre[g] = v;
            }
            const float iv = 1.0f / (1.0f + expf(-pre[0]));
            const float fv = 1.0f / (1.0f + expf(-pre[1]));
            const float gv = tanhf(pre[2]);
            const float ov = 1.0f / (1.0f + expf(-pre[3]));
            const float cp = (s > 0) ? g_c[b * HSZ + n] : 0.0f;
            const float cn = fv * cp + iv * gv;
            const float hn = ov * tanhf(cn);
            g_c[b * HSZ + n] = cn;
            out[((size_t)s * BSZ + b) * HSZ + n] = hn;
            if (s == SSZ - 1) {
                out[((size_t)SSZ       * BSZ + b) * HSZ + n] = hn;  // h_f
                out[((size_t)(SSZ + 1) * BSZ + b) * HSZ + n] = cn;  // c_f
            }
        }

        grid_barrier();   // h(s) visible -> next step
    }
}

extern "C" void kernel_launch(void* const* d_in, const int* in_sizes, int n_in,
                              void* d_out, int out_size)
{
    const float* x   = (const float*)d_in[0];
    const float* wih = (const float*)d_in[1];
    const float* whh = (const float*)d_in[2];
    const float* bih = (const float*)d_in[3];
    const float* bhh = (const float*)d_in[4];
    float* out = (float*)d_out;

    dim3 gridA(G4 / 128, (SSZ * BSZ) / 128);    // (32, 256)
    gx_gemm<<<gridA, 256>>>(x, wih, bih, bhh);

    lstm_persist<<<NBLK, 256>>>(whh, out);

    (void)in_sizes; (void)n_in; (void)out_size;
}